// round 5
// baseline (speedup 1.0000x reference)
#include <cuda_runtime.h>
#include <cuda_bf16.h>
#include <cstdint>

// Precomputed 1/(2*w^2) and per-graph contiguous row ranges (batch is sorted).
__device__ float g_inv2w2;
__device__ int   g_gs[1024];   // graph start index
__device__ int   g_ge[1024];   // graph end index (exclusive)

__global__ void msb_setup_kernel(const float* __restrict__ width,
                                 const int* __restrict__ batch, int n) {
    if (threadIdx.x == 0) {
        float w = *width;
        g_inv2w2 = 0.5f / (w * w);
    }
    // batch is sorted: record [start,end) per graph id. Absent ids never read.
    for (int idx = threadIdx.x; idx < n; idx += blockDim.x) {
        int b = batch[idx] & 1023;
        if (idx == 0     || (batch[idx - 1] & 1023) != b) g_gs[b] = idx;
        if (idx == n - 1 || (batch[idx + 1] & 1023) != b) g_ge[b] = idx + 1;
    }
}

// 4 lanes per (i,j) pair (each lane owns one float4 of the 16 rbf values),
// 2 rows i per thread for store MLP and amortized index math.
// Validity via precomputed per-graph ranges: the 94% invalid pairs do ZERO
// pos/batch[j] loads — just a contiguous STG.128 of zeros.
// Output layout (reference order): [mask (N*N), rbf (N*N*16)], fp32.
__global__ __launch_bounds__(256)
void msb_edge_kernel(const float* __restrict__ pos,
                     const int* __restrict__ batch,
                     const float* __restrict__ centers,
                     float* __restrict__ out_mask,
                     float* __restrict__ out_rbf,
                     int n)
{
    const unsigned tid = blockIdx.x * blockDim.x + threadIdx.x; // over n*4 lanes
    const int j     = (int)(tid >> 2);
    const int chunk = (int)(tid & 3);
    if (j >= n) return;

    const int c0 = chunk * 4;
    const float inv = g_inv2w2;

    // pos[j] loaded once, shared by both rows (only needed if any row valid,
    // but loading unconditionally here would hurt the all-invalid warps; defer).
    float4* __restrict__ rbf4 = reinterpret_cast<float4*>(out_rbf);

    #pragma unroll
    for (int r = 0; r < 2; ++r) {
        const int i = blockIdx.y * 2 + r;
        if (i >= n) break;

        const int b  = batch[i] & 1023;      // broadcast load
        const int lo = g_gs[b];              // broadcast load
        const int hi = g_ge[b];              // broadcast load

        const unsigned pair = (unsigned)i * (unsigned)n + (unsigned)j;

        float4 outv  = make_float4(0.f, 0.f, 0.f, 0.f);
        float  maskv = 0.0f;

        if (j >= lo && j < hi && j != i) {
            // reference: diff = pos[i]-pos[j] + 1e-10 per comp; dist = ||diff||
            float dx = pos[3 * i + 0] - pos[3 * j + 0] + 1e-10f;
            float dy = pos[3 * i + 1] - pos[3 * j + 1] + 1e-10f;
            float dz = pos[3 * i + 2] - pos[3 * j + 2] + 1e-10f;
            float d2 = dx * dx + dy * dy + dz * dz;
            if (d2 < 64.0f) {                // dist < CUTOFF(=8)
                const float d = sqrtf(d2);
                float t0 = d - __ldg(&centers[c0 + 0]);
                float t1 = d - __ldg(&centers[c0 + 1]);
                float t2 = d - __ldg(&centers[c0 + 2]);
                float t3 = d - __ldg(&centers[c0 + 3]);
                outv = make_float4(__expf(-t0 * t0 * inv),
                                   __expf(-t1 * t1 * inv),
                                   __expf(-t2 * t2 * inv),
                                   __expf(-t3 * t3 * inv));
                maskv = 1.0f;
            }
        }

        rbf4[pair * 4u + (unsigned)chunk] = outv;
        if (chunk == 0) out_mask[pair] = maskv;
    }
}

extern "C" void kernel_launch(void* const* d_in, const int* in_sizes, int n_in,
                              void* d_out, int out_size)
{
    const float* pos     = (const float*)d_in[0];
    const int*   batch   = (const int*)d_in[1];
    const float* centers = (const float*)d_in[2];
    const float* width   = (const float*)d_in[3];

    const int n = in_sizes[0] / 3;          // pos is [N,3]
    const size_t nn = (size_t)n * (size_t)n;

    float* out      = (float*)d_out;
    float* out_mask = out;        // [N*N]
    float* out_rbf  = out + nn;   // [N*N*16]

    msb_setup_kernel<<<1, 256>>>(width, batch, n);

    dim3 block(256, 1, 1);
    dim3 grid((unsigned)((n * 4 + 255) / 256), (unsigned)((n + 1) / 2), 1);
    msb_edge_kernel<<<grid, block>>>(pos, batch, centers, out_mask, out_rbf, n);
}

// round 6
// speedup vs baseline: 1.2149x; 1.2149x over previous
#include <cuda_runtime.h>
#include <cuda_bf16.h>
#include <cstdint>

// Single kernel, no setup pass. 4 lanes per (i,j) pair, each lane stores one
// float4 of the 16 rbf values: warp stores are 512B fully contiguous STG.128.
// inv2w2 = 0.5/(w*w) is computed only on the valid path (~6% of warps, and
// batch is sorted so valid lanes cluster into whole warps).
// Streaming stores (__stcs): output is write-once (285MB >> L2), evict-first.
// Output layout (reference order): [mask (N*N), rbf (N*N*16)], fp32.
__global__ __launch_bounds__(256)
void msb_edge_kernel(const float* __restrict__ pos,
                     const int* __restrict__ batch,   // int32
                     const float* __restrict__ centers,
                     const float* __restrict__ width,
                     float* __restrict__ out_mask,
                     float* __restrict__ out_rbf,
                     int n)
{
    const unsigned tid = blockIdx.x * blockDim.x + threadIdx.x; // over n*4 lanes
    const int j     = (int)(tid >> 2);
    const int chunk = (int)(tid & 3);
    if (j >= n) return;

    const int i = blockIdx.y;
    // rbf float4 index: pair*4 + chunk == i*(4n) + tid  (pure 32-bit)
    const unsigned idx4 = (unsigned)i * (unsigned)(4 * n) + tid;

    const int bi = batch[i];   // broadcast load (L1-resident)
    const int bj = batch[j];   // coalesced: 8 consecutive ints per warp

    float4 outv  = make_float4(0.f, 0.f, 0.f, 0.f);
    float  maskv = 0.0f;

    if ((bi == bj) && (i != j)) {
        // reference: diff = pos[i]-pos[j] + 1e-10 per component; dist = ||diff||
        float dx = pos[3 * i + 0] - pos[3 * j + 0] + 1e-10f;
        float dy = pos[3 * i + 1] - pos[3 * j + 1] + 1e-10f;
        float dz = pos[3 * i + 2] - pos[3 * j + 2] + 1e-10f;
        float d2 = dx * dx + dy * dy + dz * dz;
        if (d2 < 64.0f) {  // dist < CUTOFF(=8); sqrt monotone
            const float d = sqrtf(d2);
            const float w = *width;                       // broadcast, cached
            const float inv = __fdividef(0.5f, w * w);    // valid path only
            const int c0 = chunk * 4;
            float t0 = d - __ldg(&centers[c0 + 0]);
            float t1 = d - __ldg(&centers[c0 + 1]);
            float t2 = d - __ldg(&centers[c0 + 2]);
            float t3 = d - __ldg(&centers[c0 + 3]);
            outv = make_float4(__expf(-t0 * t0 * inv),
                               __expf(-t1 * t1 * inv),
                               __expf(-t2 * t2 * inv),
                               __expf(-t3 * t3 * inv));
            maskv = 1.0f;
        }
    }

    __stcs(reinterpret_cast<float4*>(out_rbf) + idx4, outv);
    if (chunk == 0) {
        __stcs(out_mask + (unsigned)i * (unsigned)n + (unsigned)j, maskv);
    }
}

extern "C" void kernel_launch(void* const* d_in, const int* in_sizes, int n_in,
                              void* d_out, int out_size)
{
    const float* pos     = (const float*)d_in[0];
    const int*   batch   = (const int*)d_in[1];
    const float* centers = (const float*)d_in[2];
    const float* width   = (const float*)d_in[3];

    const int n = in_sizes[0] / 3;          // pos is [N,3]
    const size_t nn = (size_t)n * (size_t)n;

    float* out      = (float*)d_out;
    float* out_mask = out;        // [N*N]
    float* out_rbf  = out + nn;   // [N*N*16]

    dim3 block(256, 1, 1);
    dim3 grid((unsigned)((n * 4 + 255) / 256), (unsigned)n, 1);
    msb_edge_kernel<<<grid, block>>>(pos, batch, centers, width,
                                     out_mask, out_rbf, n);
}

// round 7
// speedup vs baseline: 1.2231x; 1.0067x over previous
#include <cuda_runtime.h>
#include <cuda_bf16.h>
#include <cstdint>

// 4 lanes per (i,j) pair, 2 pairs per thread.
// Warp W of row i covers pairs [16W, 16W+16): lane l -> j = 16W + (l>>2),
// chunk = l&3, and second pair j+8. Both warp-wide float4 stores are perfectly
// contiguous 512B blocks (minimal L1 wavefronts); per-warp fixed cost is
// amortized over 1KB instead of 512B, and each thread holds 2 independent
// stores in flight.
// Output layout (reference order): [mask (N*N), rbf (N*N*16)], fp32.
__global__ __launch_bounds__(256)
void msb_edge_kernel(const float* __restrict__ pos,
                     const int* __restrict__ batch,   // int32
                     const float* __restrict__ centers,
                     const float* __restrict__ width,
                     float* __restrict__ out_mask,
                     float* __restrict__ out_rbf,
                     int n)
{
    const unsigned tid = blockIdx.x * blockDim.x + threadIdx.x; // n*2 lanes/row
    const unsigned W = tid >> 5;          // warp index within row
    const unsigned l = tid & 31;
    const int   j0    = (int)((W << 4) + (l >> 2));  // first pair
    const int   j1    = j0 + 8;                      // second pair
    const int   chunk = (int)(l & 3);
    if (j1 >= n && j0 >= n) return;

    const int i = blockIdx.y;
    const int bi = batch[i];              // broadcast (L1-resident)
    const float w = *width;               // broadcast
    const int c0 = chunk * 4;
    const float cA = __ldg(&centers[c0 + 0]);
    const float cB = __ldg(&centers[c0 + 1]);
    const float cC = __ldg(&centers[c0 + 2]);
    const float cD = __ldg(&centers[c0 + 3]);

    const float px = pos[3 * i + 0];
    const float py = pos[3 * i + 1];
    const float pz = pos[3 * i + 2];

    float4* __restrict__ rbf4 = reinterpret_cast<float4*>(out_rbf);
    const unsigned rowbase = (unsigned)i * (unsigned)(4 * n);

    #pragma unroll
    for (int p = 0; p < 2; ++p) {
        const int j = (p == 0) ? j0 : j1;
        if (j >= n) break;

        float4 outv  = make_float4(0.f, 0.f, 0.f, 0.f);
        float  maskv = 0.0f;

        const int bj = batch[j];          // coalesced (8 consecutive ints/warp)
        if ((bi == bj) && (i != j)) {
            // reference: diff = pos[i]-pos[j] + 1e-10 per comp; dist = ||diff||
            float dx = px - pos[3 * j + 0] + 1e-10f;
            float dy = py - pos[3 * j + 1] + 1e-10f;
            float dz = pz - pos[3 * j + 2] + 1e-10f;
            float d2 = dx * dx + dy * dy + dz * dz;
            if (d2 < 64.0f) {             // dist < CUTOFF(=8); sqrt monotone
                const float d   = sqrtf(d2);
                const float inv = __fdividef(0.5f, w * w);
                float t0 = d - cA, t1 = d - cB, t2 = d - cC, t3 = d - cD;
                outv = make_float4(__expf(-t0 * t0 * inv),
                                   __expf(-t1 * t1 * inv),
                                   __expf(-t2 * t2 * inv),
                                   __expf(-t3 * t3 * inv));
                maskv = 1.0f;
            }
        }

        // rbf float4 index: i*4n + j*4 + chunk
        __stcs(rbf4 + (rowbase + (unsigned)j * 4u + (unsigned)chunk), outv);
        if (chunk == 0) {
            __stcs(out_mask + (unsigned)i * (unsigned)n + (unsigned)j, maskv);
        }
    }
}

extern "C" void kernel_launch(void* const* d_in, const int* in_sizes, int n_in,
                              void* d_out, int out_size)
{
    const float* pos     = (const float*)d_in[0];
    const int*   batch   = (const int*)d_in[1];
    const float* centers = (const float*)d_in[2];
    const float* width   = (const float*)d_in[3];

    const int n = in_sizes[0] / 3;          // pos is [N,3]
    const size_t nn = (size_t)n * (size_t)n;

    float* out      = (float*)d_out;
    float* out_mask = out;        // [N*N]
    float* out_rbf  = out + nn;   // [N*N*16]

    // n*2 lanes per row (each thread covers 2 pairs).
    dim3 block(256, 1, 1);
    dim3 grid((unsigned)((n * 2 + 255) / 256), (unsigned)n, 1);
    msb_edge_kernel<<<grid, block>>>(pos, batch, centers, width,
                                     out_mask, out_rbf, n);
}